// round 2
// baseline (speedup 1.0000x reference)
#include <cuda_runtime.h>
#include <stdint.h>

#define BATCH 2048
#define KTOP  32
#define DDIM  768
#define DICT  24576
#define CONN  64

#define MAXPAIRS (BATCH * KTOP * KTOP)   // absolute worst case

__device__ float g_bias[DICT];
__device__ unsigned g_npairs;
// pair record: x = out position (b*K+i), y = down dict idx, z = up dict idx,
//              w = float bits of (mult * up_val)
__device__ uint4 g_pairs[MAXPAIRS];

// ---------------------------------------------------------------------------
// Kernel 1: b_dec_contrib = up_encoder_w @ b_dec (warp per row); zero counter.
// ---------------------------------------------------------------------------
__global__ __launch_bounds__(256) void bias_kernel(
    const float* __restrict__ up_encoder_w,   // [DICT, D]
    const float* __restrict__ b_dec)          // [D]
{
    if (blockIdx.x == 0 && threadIdx.x == 0) g_npairs = 0;

    __shared__ float s_b[DDIM];
    for (int i = threadIdx.x; i < DDIM; i += blockDim.x) s_b[i] = b_dec[i];
    __syncthreads();

    int warp = threadIdx.x >> 5;
    int lane = threadIdx.x & 31;
    int row  = blockIdx.x * (blockDim.x >> 5) + warp;
    if (row >= DICT) return;

    const float4* w  = reinterpret_cast<const float4*>(up_encoder_w + (size_t)row * DDIM);
    const float4* bb = reinterpret_cast<const float4*>(s_b);
    float acc = 0.f;
#pragma unroll
    for (int k = 0; k < DDIM / 128; k++) {           // 6 iterations
        float4 v = w[lane + 32 * k];
        float4 b = bb[lane + 32 * k];
        acc += v.x * b.x + v.y * b.y + v.z * b.z + v.w * b.w;
    }
#pragma unroll
    for (int o = 16; o > 0; o >>= 1) acc += __shfl_xor_sync(0xffffffffu, acc, o);
    if (lane == 0) g_bias[row] = acc;
}

// ---------------------------------------------------------------------------
// Kernel 2: matching. One block per batch element. Emits global pair records,
// writes the bias base into out.
// ---------------------------------------------------------------------------
#define HSZ 64

__global__ __launch_bounds__(128) void match_kernel(
    const float* __restrict__ up_vals,        // [B, K]
    const int*   __restrict__ up_indices,     // [B, K]
    const int*   __restrict__ down_indices,   // [B, K]
    const int*   __restrict__ connections,    // [DICT, C]
    float*       __restrict__ out)            // [B, K]
{
    __shared__ int   s_up_idx[KTOP];
    __shared__ float s_up_val[KTOP];
    __shared__ int   s_down_idx[KTOP];
    __shared__ int   s_hkey[HSZ];
    __shared__ int   s_hj[HSZ];
    __shared__ int   s_mult[KTOP * KTOP];

    const int b = blockIdx.x;
    const int t = threadIdx.x;

    if (t < KTOP) {
        s_up_idx[t]   = up_indices[b * KTOP + t];
        s_up_val[t]   = up_vals[b * KTOP + t];
        s_down_idx[t] = down_indices[b * KTOP + t];
    }
    if (t < HSZ) s_hkey[t] = -1;
    for (int e = t; e < KTOP * KTOP; e += blockDim.x) s_mult[e] = 0;
    __syncthreads();

    // Hash table of up indices (duplicates each get their own slot).
    if (t < KTOP) {
        int key = s_up_idx[t];
        unsigned p = ((unsigned)key * 2654435761u) >> 26;
        while (true) {
            int old = atomicCAS(&s_hkey[p & (HSZ - 1)], -1, key);
            if (old == -1) { s_hj[p & (HSZ - 1)] = t; break; }
            p++;
        }
    }
    __syncthreads();

    // Stream connection slots through the hash table.
    for (int item = t; item < KTOP * (CONN / 4); item += blockDim.x) {
        int i = item >> 4;
        int q = item & 15;
        int di = s_down_idx[i];
        int4 a = reinterpret_cast<const int4*>(connections + (size_t)di * CONN)[q];
        int av[4] = {a.x, a.y, a.z, a.w};
#pragma unroll
        for (int s = 0; s < 4; s++) {
            int v = av[s];
            if (v < 0) continue;
            unsigned p = ((unsigned)v * 2654435761u) >> 26;
            while (true) {
                int k = s_hkey[p & (HSZ - 1)];
                if (k == -1) break;
                if (k == v) atomicAdd(&s_mult[i * KTOP + s_hj[p & (HSZ - 1)]], 1);
                p++;
            }
        }
    }
    __syncthreads();

    // Emit nonzero pairs to the global list.
    for (int e = t; e < KTOP * KTOP; e += blockDim.x) {
        int m = s_mult[e];
        if (m != 0) {
            int i = e >> 5;
            int j = e & 31;
            unsigned p = atomicAdd(&g_npairs, 1u);
            uint4 rec;
            rec.x = (unsigned)(b * KTOP + i);
            rec.y = (unsigned)s_down_idx[i];
            rec.z = (unsigned)s_up_idx[j];
            rec.w = __float_as_uint((float)m * s_up_val[j]);
            g_pairs[p] = rec;
        }
    }

    // Bias base for the output.
    if (t < KTOP)
        out[b * KTOP + t] = g_bias[s_up_idx[t]];
}

// ---------------------------------------------------------------------------
// Kernel 3: one warp per pair record, grid-stride. Perfect load balance.
// ---------------------------------------------------------------------------
__global__ __launch_bounds__(256) void pair_kernel(
    const float* __restrict__ up_decoder_w,   // [D, DICT]  (column access)
    const float* __restrict__ down_encoder_w, // [DICT, D]  (row access)
    float*       __restrict__ out)            // [B, K]
{
    const unsigned np = g_npairs;
    const int lane = threadIdx.x & 31;
    const unsigned warp_id = (blockIdx.x * (blockDim.x >> 5)) + (threadIdx.x >> 5);
    const unsigned nwarps  = gridDim.x * (blockDim.x >> 5);

    for (unsigned p = warp_id; p < np; p += nwarps) {
        uint4 rec = g_pairs[p];
        const float* drow = down_encoder_w + (size_t)rec.y * DDIM;   // coalesced
        const float* ucol = up_decoder_w + rec.z;                    // stride DICT
        float a0 = 0.f, a1 = 0.f;
#pragma unroll
        for (int k = 0; k < DDIM / 64; k++) {        // 12 iters, 2 indep chains
            int d0 = lane + 64 * k;
            int d1 = d0 + 32;
            a0 += drow[d0] * ucol[(size_t)d0 * DICT];
            a1 += drow[d1] * ucol[(size_t)d1 * DICT];
        }
        float acc = a0 + a1;
#pragma unroll
        for (int o = 16; o > 0; o >>= 1) acc += __shfl_xor_sync(0xffffffffu, acc, o);
        if (lane == 0)
            atomicAdd(&out[rec.x], acc * __uint_as_float(rec.w));
    }
}

// ---------------------------------------------------------------------------
extern "C" void kernel_launch(void* const* d_in, const int* in_sizes, int n_in,
                              void* d_out, int out_size)
{
    const float* up_vals        = (const float*)d_in[0];
    const float* up_decoder_w   = (const float*)d_in[1];
    const float* down_encoder_w = (const float*)d_in[2];
    const float* up_encoder_w   = (const float*)d_in[3];
    const float* b_dec          = (const float*)d_in[4];
    const int*   up_indices     = (const int*)d_in[5];
    const int*   down_indices   = (const int*)d_in[6];
    const int*   connections    = (const int*)d_in[7];
    float*       out            = (float*)d_out;

    bias_kernel<<<DICT / 8, 256>>>(up_encoder_w, b_dec);
    match_kernel<<<BATCH, 128>>>(up_vals, up_indices, down_indices,
                                 connections, out);
    pair_kernel<<<1024, 256>>>(up_decoder_w, down_encoder_w, out);
}